// round 3
// baseline (speedup 1.0000x reference)
#include <cuda_runtime.h>
#include <math.h>

#define TPB 256
constexpr int CDIM  = 128;
constexpr int WSZ   = 7;
constexpr int TOK   = 49;
constexpr int HIMG  = 56;
constexpr int NPIX  = 3136;
constexpr float SCALE_F = 0.25f;
constexpr float LN_EPS  = 1e-5f;

// Shared memory layout (floats)
constexpr int SXS      = 132;                 // sX row stride (float4-aligned, conflict-irrelevant: broadcast reads)
constexpr int SX_F     = 64 * SXS;            // 8448
constexpr int SB_F     = 128 * 128;           // 16384 (weight chunk, k-major [128][128])
constexpr int SQKV_OFF = SX_F + SB_F;         // 24832
constexpr int SMEM_F   = SQKV_OFF + 64 * 384; // 49408 floats = 197632 bytes
// Phase-C per-warp scratch overlays sX+sB region: K(49x18) + V(49x18) + P(49)
constexpr int KVW = 1824;                     // 8*1824 = 14592 < 24832

using u64 = unsigned long long;
__device__ __forceinline__ u64 pk2(float lo, float hi) {
    u64 r; asm("mov.b64 %0,{%1,%2};" : "=l"(r) : "f"(lo), "f"(hi)); return r;
}
__device__ __forceinline__ void fma2(u64& d, u64 a, u64 b) {
    asm("fma.rn.f32x2 %0,%1,%2,%3;" : "=l"(d) : "l"(a), "l"(b), "l"(d));
}
__device__ __forceinline__ void upk2(u64 v, float& lo, float& hi) {
    asm("mov.b64 {%0,%1},%2;" : "=f"(lo), "=f"(hi) : "l"(v));
}

// C[64x128] += A[64x128] @ B[128x128]; A k-major stride lda, B k-major [k][128].
// Thread tile: 8 rows (rowg = tid>>5) x 4 cols as 2 f32x2 (colg = tid&31).
__device__ __forceinline__ void gemm64x128_f32x2(const float* __restrict__ sA, int lda,
                                                 const float* __restrict__ sB,
                                                 int rowg, int colg, u64 acc[8][2]) {
    const float* aBase = sA + rowg * 8 * lda;
    const float* bBase = sB + colg * 4;
    #pragma unroll 4
    for (int k0 = 0; k0 < 128; k0 += 4) {
        float4 rA[8];
        #pragma unroll
        for (int i = 0; i < 8; ++i)
            rA[i] = *reinterpret_cast<const float4*>(&aBase[i * lda + k0]);
        #pragma unroll
        for (int kk = 0; kk < 4; ++kk) {
            float4 b = *reinterpret_cast<const float4*>(&bBase[(k0 + kk) * 128]);
            u64 b01 = pk2(b.x, b.y), b23 = pk2(b.z, b.w);
            #pragma unroll
            for (int i = 0; i < 8; ++i) {
                float a = reinterpret_cast<const float*>(&rA[i])[kk];
                u64 a2 = pk2(a, a);
                fma2(acc[i][0], a2, b01);
                fma2(acc[i][1], a2, b23);
            }
        }
    }
}

__global__ __launch_bounds__(TPB, 1)
void swin_window_attn_kernel(const float* __restrict__ x,
                             const float* __restrict__ ln_g,
                             const float* __restrict__ ln_b,
                             const float* __restrict__ wqkv,
                             const float* __restrict__ bqkv,
                             const float* __restrict__ wout,
                             const float* __restrict__ bout,
                             float* __restrict__ out) {
    extern __shared__ float sm[];
    float* sX   = sm;              // [64][132] normalized input (rows 49..63 zero)
    float* sB   = sm + SX_F;       // [128][128] weight chunk, k-major
    float* sQKV = sm + SQKV_OFF;   // [64][384] qkv; attn-out overwrites cols [0,128)

    const int tid  = threadIdx.x;
    const int wid  = tid >> 5;
    const int lane = tid & 31;
    const int w    = blockIdx.x;
    const int b    = w >> 6;
    const int wy   = (w >> 3) & 7;
    const int wx   = w & 7;

    // ---------------- Phase A: LayerNorm (warp per token) ----------------
    {
        float4 gg = *reinterpret_cast<const float4*>(&ln_g[lane * 4]);
        float4 bb = *reinterpret_cast<const float4*>(&ln_b[lane * 4]);
        for (int t = wid; t < TOK; t += 8) {
            int r    = wy * WSZ + t / WSZ;
            int cpos = wx * WSZ + t % WSZ;
            const float* xr = x + (size_t)(b * NPIX + r * HIMG + cpos) * CDIM;
            float4 v = *reinterpret_cast<const float4*>(&xr[lane * 4]);
            float s = v.x + v.y + v.z + v.w;
            float q = v.x * v.x + v.y * v.y + v.z * v.z + v.w * v.w;
            #pragma unroll
            for (int off = 16; off; off >>= 1) {
                s += __shfl_xor_sync(0xffffffffu, s, off);
                q += __shfl_xor_sync(0xffffffffu, q, off);
            }
            float mu  = s * (1.f / 128.f);
            float var = q * (1.f / 128.f) - mu * mu;
            float rs  = rsqrtf(var + LN_EPS);
            float* dst = &sX[t * SXS + lane * 4];
            float4 o;
            o.x = (v.x - mu) * rs * gg.x + bb.x;
            o.y = (v.y - mu) * rs * gg.y + bb.y;
            o.z = (v.z - mu) * rs * gg.z + bb.z;
            o.w = (v.w - mu) * rs * gg.w + bb.w;
            *reinterpret_cast<float4*>(dst) = o;
        }
        for (int p = tid; p < 15 * SXS; p += TPB) sX[TOK * SXS + p] = 0.f;
    }

    const int rowg = tid >> 5;   // 0..7 : 8 rows each
    const int colg = tid & 31;   // 0..31 : 4 cols each

    // ---------------- Phase B: QKV GEMM [64x384] = sX @ wqkv, 3 chunks of N=128 ----------------
    for (int ch = 0; ch < 3; ++ch) {
        __syncthreads();
        for (int f = tid; f < 4096; f += TPB) {
            int k = f >> 5, j = f & 31;
            *reinterpret_cast<float4*>(&sB[k * 128 + j * 4]) =
                *reinterpret_cast<const float4*>(&wqkv[k * 384 + ch * 128 + j * 4]);
        }
        __syncthreads();
        u64 acc[8][2] = {};
        gemm64x128_f32x2(sX, SXS, sB, rowg, colg, acc);
        float4 bv = *reinterpret_cast<const float4*>(&bqkv[ch * 128 + colg * 4]);
        #pragma unroll
        for (int i = 0; i < 8; ++i) {
            float x0, x1, y0, y1;
            upk2(acc[i][0], x0, x1);
            upk2(acc[i][1], y0, y1);
            *reinterpret_cast<float4*>(&sQKV[(rowg * 8 + i) * 384 + ch * 128 + colg * 4]) =
                make_float4(x0 + bv.x, x1 + bv.y, y0 + bv.z, y1 + bv.w);
        }
    }
    __syncthreads();

    // ---------------- Phase C: attention, warp `wid` owns head `wid` ----------------
    {
        float* sK = sm + wid * KVW;   // [49][18]
        float* sV = sK + 882;         // [49][18]
        float* sP = sK + 1764;        // [49]
        for (int p = lane; p < TOK * 16; p += 32) {
            int t = p >> 4, d = p & 15;
            sK[t * 18 + d] = sQKV[t * 384 + 128 + wid * 16 + d];
            sV[t * 18 + d] = sQKV[t * 384 + 256 + wid * 16 + d];
        }
        __syncwarp();
        const int dp = lane & 7, h4 = lane >> 3;
        const u64* k0p = reinterpret_cast<const u64*>(&sK[lane * 18]);
        const u64* k1p = reinterpret_cast<const u64*>(&sK[(lane + 32) * 18]);  // may read junk; gated below
        for (int qt = 0; qt < TOK; ++qt) {
            const float* qrow = &sQKV[qt * 384 + wid * 16];
            const u64* q2 = reinterpret_cast<const u64*>(qrow);
            u64 a0 = 0ull, a1 = 0ull;
            #pragma unroll
            for (int j = 0; j < 8; ++j) {
                u64 qv = q2[j];
                fma2(a0, qv, k0p[j]);
                fma2(a1, qv, k1p[j]);
            }
            float s0a, s0b, s1a, s1b;
            upk2(a0, s0a, s0b);
            upk2(a1, s1a, s1b);
            float e0 = __expf((s0a + s0b) * SCALE_F);                       // kt = lane (<49)
            float e1 = (lane < 17) ? __expf((s1a + s1b) * SCALE_F) : 0.f;   // kt = lane+32
            float ssum = e0 + e1;
            #pragma unroll
            for (int off = 16; off; off >>= 1)
                ssum += __shfl_xor_sync(0xffffffffu, ssum, off);
            float inv = __frcp_rn(ssum);
            sP[lane] = e0;
            if (lane < 17) sP[lane + 32] = e1;
            __syncwarp();
            // O[qt][2dp..2dp+1]: lanes split kt mod 4 via h4, 13 iters of FFMA2
            u64 o2 = 0ull;
            #pragma unroll
            for (int i = 0; i < 13; ++i) {
                int kt = h4 + 4 * i;
                if (kt < TOK) {
                    float p = sP[kt];
                    u64 v2 = *reinterpret_cast<const u64*>(&sV[kt * 18 + 2 * dp]);
                    fma2(o2, pk2(p, p), v2);
                }
            }
            float olo, ohi;
            upk2(o2, olo, ohi);
            olo += __shfl_xor_sync(0xffffffffu, olo, 8);
            ohi += __shfl_xor_sync(0xffffffffu, ohi, 8);
            olo += __shfl_xor_sync(0xffffffffu, olo, 16);
            ohi += __shfl_xor_sync(0xffffffffu, ohi, 16);
            if (lane < 8)
                *reinterpret_cast<float2*>(&sQKV[qt * 384 + wid * 16 + 2 * dp]) =
                    make_float2(olo * inv, ohi * inv);
            __syncwarp();
        }
    }
    __syncthreads();

    // ---------------- Phase D: out projection [49x128] = attn[64x128] @ wout[128x128] ----------------
    {
        for (int f = tid; f < 4096; f += TPB) {
            int k = f >> 5, j = f & 31;
            *reinterpret_cast<float4*>(&sB[k * 128 + j * 4]) =
                *reinterpret_cast<const float4*>(&wout[k * 128 + j * 4]);
        }
        __syncthreads();
        u64 acc[8][2] = {};
        gemm64x128_f32x2(sQKV, 384, sB, rowg, colg, acc);
        float4 bo = *reinterpret_cast<const float4*>(&bout[colg * 4]);
        #pragma unroll
        for (int i = 0; i < 8; ++i) {
            int m = rowg * 8 + i;
            if (m < TOK) {
                int r    = wy * WSZ + m / WSZ;
                int cpos = wx * WSZ + m % WSZ;
                float x0, x1, y0, y1;
                upk2(acc[i][0], x0, x1);
                upk2(acc[i][1], y0, y1);
                *reinterpret_cast<float4*>(
                    out + (size_t)(b * NPIX + r * HIMG + cpos) * CDIM + colg * 4) =
                    make_float4(x0 + bo.x, x1 + bo.y, y0 + bo.z, y1 + bo.w);
            }
        }
    }
}

extern "C" void kernel_launch(void* const* d_in, const int* in_sizes, int n_in,
                              void* d_out, int out_size) {
    const float* x    = (const float*)d_in[0];
    const float* g    = (const float*)d_in[1];
    const float* bt   = (const float*)d_in[2];
    const float* wqkv = (const float*)d_in[3];
    const float* bqkv = (const float*)d_in[4];
    const float* wout = (const float*)d_in[5];
    const float* bout = (const float*)d_in[6];
    float* out = (float*)d_out;

    const int smem_bytes = SMEM_F * (int)sizeof(float);  // 197632
    cudaFuncSetAttribute(swin_window_attn_kernel,
                         cudaFuncAttributeMaxDynamicSharedMemorySize, smem_bytes);
    swin_window_attn_kernel<<<4096, TPB, smem_bytes>>>(x, g, bt, wqkv, bqkv, wout, bout, out);
}

// round 7
// speedup vs baseline: 1.1612x; 1.1612x over previous
#include <cuda_runtime.h>
#include <cuda_bf16.h>

using u32 = unsigned int; using u64 = unsigned long long;
#define TPB 256
constexpr int WSZ = 7, HIMG = 56, NPIX = 3136, CDIM = 128;
constexpr float SCALE_F = 0.25f, LN_EPS = 1e-5f;

// smem layout (bytes)
constexpr int AST = 272;                       // A/A2 tile row stride (136 bf16)
constexpr int WST = 144;                       // W tile row stride (72 bf16)
constexpr int OFF_AH = 0, OFF_AL = 17408;      // X / attn-out tiles, 64 rows
constexpr int OFF_WH = 34816, OFF_WL = 53248;  // W chunk tiles, 128 rows
constexpr int OFF_S  = 71680;                  // QKV fp32 [64 rows][386]
constexpr int SST = 386;                       // (386*lane)%32=2lane -> 2-way only
constexpr int OFF_SP = OFF_S + 64 * SST * 4;   // 170496: 8 warps x 52 floats
constexpr int SMEM_BYTES = OFF_SP + 8 * 52 * 4;  // 172160

__device__ __forceinline__ u32 smem_u32(const void* p) {
    u32 a; asm("{ .reg .u64 t; cvta.to.shared.u64 t, %1; cvt.u32.u64 %0, t; }" : "=r"(a) : "l"(p));
    return a;
}
__device__ __forceinline__ void split2(float a, float b, u32& hi, u32& lo) {
    __nv_bfloat16 ha = __float2bfloat16(a), hb = __float2bfloat16(b);
    __nv_bfloat16 la = __float2bfloat16(a - __bfloat162float(ha));
    __nv_bfloat16 lb = __float2bfloat16(b - __bfloat162float(hb));
    hi = (u32)__bfloat16_as_ushort(ha) | ((u32)__bfloat16_as_ushort(hb) << 16);
    lo = (u32)__bfloat16_as_ushort(la) | ((u32)__bfloat16_as_ushort(lb) << 16);
}
__device__ __forceinline__ u64 pk2(float lo, float hi) {
    u64 r; asm("mov.b64 %0,{%1,%2};" : "=l"(r) : "f"(lo), "f"(hi)); return r;
}
__device__ __forceinline__ void fma2(u64& d, u64 a, u64 b) {
    asm("fma.rn.f32x2 %0,%1,%2,%3;" : "=l"(d) : "l"(a), "l"(b), "l"(d));
}
__device__ __forceinline__ void upk2(u64 v, float& lo, float& hi) {
    asm("mov.b64 {%0,%1},%2;" : "=f"(lo), "=f"(hi) : "l"(v));
}
__device__ __forceinline__ void ldsm4(u32 a[4], u32 addr) {
    asm volatile("ldmatrix.sync.aligned.m8n8.x4.shared.b16 {%0,%1,%2,%3},[%4];"
        : "=r"(a[0]), "=r"(a[1]), "=r"(a[2]), "=r"(a[3]) : "r"(addr));
}
__device__ __forceinline__ void ldsm2t(u32 b[2], u32 addr) {
    asm volatile("ldmatrix.sync.aligned.m8n8.x2.trans.shared.b16 {%0,%1},[%2];"
        : "=r"(b[0]), "=r"(b[1]) : "r"(addr));
}
__device__ __forceinline__ void mma16816(float d[4], const u32 a[4], const u32 b[2]) {
    asm volatile("mma.sync.aligned.m16n8k16.row.col.f32.bf16.bf16.f32 "
        "{%0,%1,%2,%3},{%4,%5,%6,%7},{%8,%9},{%0,%1,%2,%3};"
        : "+f"(d[0]), "+f"(d[1]), "+f"(d[2]), "+f"(d[3])
        : "r"(a[0]), "r"(a[1]), "r"(a[2]), "r"(a[3]), "r"(b[0]), "r"(b[1]));
}
// load [128k x 64n] fp32 chunk of W -> split bf16 hi/lo padded tiles
__device__ __forceinline__ void load_w(char* smc, const float* __restrict__ W,
                                       int ldw, int cb, int tid) {
    #pragma unroll
    for (int i = 0; i < 8; ++i) {
        int f = tid + i * TPB;            // 0..2047
        int k = f >> 4, j4 = (f & 15) * 4;
        float4 w = *reinterpret_cast<const float4*>(W + (size_t)k * ldw + cb + j4);
        u32 h0, l0, h1, l1;
        split2(w.x, w.y, h0, l0); split2(w.z, w.w, h1, l1);
        char* p = smc + k * WST + j4 * 2;
        *reinterpret_cast<uint2*>(p + OFF_WH) = make_uint2(h0, h1);
        *reinterpret_cast<uint2*>(p + OFF_WL) = make_uint2(l0, l1);
    }
}
// C[64 x 64] += A(split)[64x128] @ W(split)[128x64]; warp covers 16 rows x 32 cols
__device__ __forceinline__ void gemm_chunk(u32 smb, int lane, int mband, int nhalf,
                                           float d[4][4]) {
    u32 aH = smb + OFF_AH + (mband * 16 + (lane & 15)) * AST + (lane >> 4) * 16;
    u32 aL = aH + (OFF_AL - OFF_AH);
    u32 bRow = smb + OFF_WH + (lane & 15) * WST + nhalf * 64;
    #pragma unroll
    for (int ks = 0; ks < 8; ++ks) {
        u32 ah[4], al[4];
        ldsm4(ah, aH + ks * 32);
        ldsm4(al, aL + ks * 32);
        #pragma unroll
        for (int nt = 0; nt < 4; ++nt) {
            u32 bh[2], bl[2];
            u32 ba = bRow + ks * 16 * WST + nt * 16;
            ldsm2t(bh, ba);
            ldsm2t(bl, ba + (OFF_WL - OFF_WH));
            mma16816(d[nt], ah, bh);
            mma16816(d[nt], ah, bl);
            mma16816(d[nt], al, bh);
        }
    }
}

__global__ __launch_bounds__(TPB, 1)
void swin_mma_kernel(const float* __restrict__ x,
                     const float* __restrict__ ln_g, const float* __restrict__ ln_b,
                     const float* __restrict__ wqkv, const float* __restrict__ bqkv,
                     const float* __restrict__ wout, const float* __restrict__ bout,
                     float* __restrict__ out) {
    extern __shared__ char smc[];
    float* smf = reinterpret_cast<float*>(smc);
    const u32 smb = smem_u32(smc);
    const int tid = threadIdx.x, wid = tid >> 5, lane = tid & 31;
    const int w = blockIdx.x, b = w >> 6, wy = (w >> 3) & 7, wx = w & 7;

    // ---- Phase A: LayerNorm -> split-bf16 X tiles (rows 49..63 stale: harmless) ----
    {
        float4 gg = *reinterpret_cast<const float4*>(&ln_g[lane * 4]);
        float4 bb = *reinterpret_cast<const float4*>(&ln_b[lane * 4]);
        for (int t = wid; t < 49; t += 8) {
            int r = wy * WSZ + t / WSZ, cp = wx * WSZ + t % WSZ;
            const float* xr = x + (size_t)(b * NPIX + r * HIMG + cp) * CDIM;
            float4 v = *reinterpret_cast<const float4*>(&xr[lane * 4]);
            float s = v.x + v.y + v.z + v.w;
            float q = v.x * v.x + v.y * v.y + v.z * v.z + v.w * v.w;
            #pragma unroll
            for (int o = 16; o; o >>= 1) {
                s += __shfl_xor_sync(0xffffffffu, s, o);
                q += __shfl_xor_sync(0xffffffffu, q, o);
            }
            float mu = s * (1.f / 128.f);
            float rs = rsqrtf(q * (1.f / 128.f) - mu * mu + LN_EPS);
            u32 h0, l0, h1, l1;
            split2((v.x - mu) * rs * gg.x + bb.x, (v.y - mu) * rs * gg.y + bb.y, h0, l0);
            split2((v.z - mu) * rs * gg.z + bb.z, (v.w - mu) * rs * gg.w + bb.w, h1, l1);
            char* p = smc + t * AST + lane * 8;
            *reinterpret_cast<uint2*>(p + OFF_AH) = make_uint2(h0, h1);
            *reinterpret_cast<uint2*>(p + OFF_AL) = make_uint2(l0, l1);
        }
    }
    __syncthreads();

    const int mband = wid >> 1, nhalf = wid & 1, tig = lane & 3, g = lane >> 2;

    // ---- Phase B: QKV GEMM, 6 chunks of N=64, D -> S fp32 (+bias) ----
    for (int ch = 0; ch < 6; ++ch) {
        load_w(smc, wqkv, 384, ch * 64, tid);
        __syncthreads();
        float d[4][4] = {};
        gemm_chunk(smb, lane, mband, nhalf, d);
        int R0 = mband * 16 + g, R1 = R0 + 8;
        #pragma unroll
        for (int nt = 0; nt < 4; ++nt) {
            int n = ch * 64 + nhalf * 32 + nt * 8 + 2 * tig;
            float2 bq = *reinterpret_cast<const float2*>(bqkv + n);
            if (R0 < 49)
                *reinterpret_cast<float2*>(&smf[OFF_S / 4 + R0 * SST + n]) =
                    make_float2(d[nt][0] + bq.x, d[nt][1] + bq.y);
            if (R1 < 49)
                *reinterpret_cast<float2*>(&smf[OFF_S / 4 + R1 * SST + n]) =
                    make_float2(d[nt][2] + bq.x, d[nt][3] + bq.y);
        }
        __syncthreads();
    }

    // ---- Phase C: attention, warp `wid` = head; output -> split-bf16 A2 tiles ----
    {
        float* S = smf + OFF_S / 4;
        float* sP = smf + OFF_SP / 4 + wid * 52;
        const u64* k0p = reinterpret_cast<const u64*>(&S[lane * SST + 128 + wid * 16]);
        const u64* k1p = reinterpret_cast<const u64*>(&S[(lane + 32) * SST + 128 + wid * 16]);
        const int dp = lane & 7, h4 = lane >> 3;
        for (int qt = 0; qt < 49; ++qt) {
            const u64* q2 = reinterpret_cast<const u64*>(&S[qt * SST + wid * 16]);
            u64 a0 = 0ull, a1 = 0ull;
            #pragma unroll
            for (int j = 0; j < 8; ++j) { u64 qv = q2[j]; fma2(a0, qv, k0p[j]); fma2(a1, qv, k1p[j]); }
            float s0a, s0b, s1a, s1b;
            upk2(a0, s0a, s0b); upk2(a1, s1a, s1b);
            float e0 = __expf((s0a + s0b) * SCALE_F);
            float e1 = (lane < 17) ? __expf((s1a + s1b) * SCALE_F) : 0.f;
            float ssum = e0 + e1;
            #pragma unroll
            for (int o = 16; o; o >>= 1) ssum += __shfl_xor_sync(0xffffffffu, ssum, o);
            float inv = __frcp_rn(ssum);
            sP[lane] = e0;
            if (lane < 17) sP[lane + 32] = e1;
            __syncwarp();
            u64 o2 = 0ull;
            #pragma unroll
            for (int i = 0; i < 13; ++i) {
                int kt = h4 + 4 * i;
                if (kt < 49) {
                    float p = sP[kt];
                    u64 v2 = *reinterpret_cast<const u64*>(&S[kt * SST + 256 + wid * 16 + 2 * dp]);
                    fma2(o2, pk2(p, p), v2);
                }
            }
            float olo, ohi;
            upk2(o2, olo, ohi);
            olo += __shfl_xor_sync(0xffffffffu, olo, 8);
            ohi += __shfl_xor_sync(0xffffffffu, ohi, 8);
            olo += __shfl_xor_sync(0xffffffffu, olo, 16);
            ohi += __shfl_xor_sync(0xffffffffu, ohi, 16);
            if (lane < 8) {
                u32 hi, lo;
                split2(olo * inv, ohi * inv, hi, lo);
                char* p = smc + qt * AST + (wid * 16 + 2 * dp) * 2;
                *reinterpret_cast<u32*>(p + OFF_AH) = hi;
                *reinterpret_cast<u32*>(p + OFF_AL) = lo;
            }
            __syncwarp();
        }
    }
    __syncthreads();

    // ---- Phase D: out-proj, 2 chunks of N=64, D -> gmem (+bias) ----
    for (int ch = 0; ch < 2; ++ch) {
        load_w(smc, wout, 128, ch * 64, tid);
        __syncthreads();
        float d[4][4] = {};
        gemm_chunk(smb, lane, mband, nhalf, d);
        int R0 = mband * 16 + g, R1 = R0 + 8;
        #pragma unroll
        for (int nt = 0; nt < 4; ++nt) {
            int n = ch * 64 + nhalf * 32 + nt * 8 + 2 * tig;
            float2 bo = *reinterpret_cast<const float2*>(bout + n);
            if (R0 < 49) {
                int r = wy * WSZ + R0 / WSZ, cp = wx * WSZ + R0 % WSZ;
                *reinterpret_cast<float2*>(out + (size_t)(b * NPIX + r * HIMG + cp) * CDIM + n) =
                    make_float2(d[nt][0] + bo.x, d[nt][1] + bo.y);
            }
            if (R1 < 49) {
                int r = wy * WSZ + R1 / WSZ, cp = wx * WSZ + R1 % WSZ;
                *reinterpret_cast<float2*>(out + (size_t)(b * NPIX + r * HIMG + cp) * CDIM + n) =
                    make_float2(d[nt][2] + bo.x, d[nt][3] + bo.y);
            }
        }
        __syncthreads();
    }
}

extern "C" void kernel_launch(void* const* d_in, const int* in_sizes, int n_in,
                              void* d_out, int out_size) {
    const float* x    = (const float*)d_in[0];
    const float* g    = (const float*)d_in[1];
    const float* bt   = (const float*)d_in[2];
    const float* wqkv = (const float*)d_in[3];
    const float* bqkv = (const float*)d_in[4];
    const float* wout = (const float*)d_in[5];
    const float* bout = (const float*)d_in[6];
    float* out = (float*)d_out;
    cudaFuncSetAttribute(swin_mma_kernel,
                         cudaFuncAttributeMaxDynamicSharedMemorySize, SMEM_BYTES);
    swin_mma_kernel<<<4096, TPB, SMEM_BYTES>>>(x, g, bt, wqkv, bqkv, wout, bout, out);
}

// round 8
// speedup vs baseline: 1.7470x; 1.5045x over previous
#include <cuda_runtime.h>
#include <cuda_bf16.h>

using u32 = unsigned int; using u64 = unsigned long long;
#define TPB 256
constexpr int WSZ = 7, HIMG = 56, NPIX = 3136, CDIM = 128;
constexpr float SCALE_F = 0.25f, LN_EPS = 1e-5f;

// smem layout (bytes)
constexpr int AST = 272;                       // A/A2 tile row stride (136 bf16)
constexpr int WST = 144;                       // W tile row stride (72 bf16)
constexpr int OFF_AH = 0, OFF_AL = 17408;      // X / attn-out tiles, 64 rows
constexpr int OFF_WH = 34816, OFF_WL = 53248;  // W chunk tiles, 128 rows
constexpr int OFF_S  = 71680;                  // QKV fp32 [64 rows][386]
constexpr int SST = 386;
constexpr int SMEM_BYTES = OFF_S + 64 * SST * 4;  // 170496

__device__ __forceinline__ u32 smem_u32(const void* p) {
    u32 a; asm("{ .reg .u64 t; cvta.to.shared.u64 t, %1; cvt.u32.u64 %0, t; }" : "=r"(a) : "l"(p));
    return a;
}
__device__ __forceinline__ void split2(float a, float b, u32& hi, u32& lo) {
    __nv_bfloat16 ha = __float2bfloat16(a), hb = __float2bfloat16(b);
    __nv_bfloat16 la = __float2bfloat16(a - __bfloat162float(ha));
    __nv_bfloat16 lb = __float2bfloat16(b - __bfloat162float(hb));
    hi = (u32)__bfloat16_as_ushort(ha) | ((u32)__bfloat16_as_ushort(hb) << 16);
    lo = (u32)__bfloat16_as_ushort(la) | ((u32)__bfloat16_as_ushort(lb) << 16);
}
__device__ __forceinline__ u64 pk2(float lo, float hi) {
    u64 r; asm("mov.b64 %0,{%1,%2};" : "=l"(r) : "f"(lo), "f"(hi)); return r;
}
__device__ __forceinline__ void fma2(u64& d, u64 a, u64 b) {
    asm("fma.rn.f32x2 %0,%1,%2,%3;" : "=l"(d) : "l"(a), "l"(b), "l"(d));
}
__device__ __forceinline__ void upk2(u64 v, float& lo, float& hi) {
    asm("mov.b64 {%0,%1},%2;" : "=f"(lo), "=f"(hi) : "l"(v));
}
// MUFU-free e^x: 2^(x*log2e), deg-5 poly + exponent bit assembly (all FMA/ALU pipe)
__device__ __forceinline__ float fexp(float x) {
    float y = fminf(fmaxf(x * 1.44269504f, -126.f), 126.f);
    int ni = __float2int_rn(y);
    float f = y - (float)ni;
    float p = 1.33336e-3f;
    p = fmaf(p, f, 9.61813e-3f);
    p = fmaf(p, f, 5.550411e-2f);
    p = fmaf(p, f, 2.4022651e-1f);
    p = fmaf(p, f, 6.9314718e-1f);
    p = fmaf(p, f, 1.0f);
    return p * __int_as_float((ni + 127) << 23);
}
__device__ __forceinline__ void ldsm4(u32 a[4], u32 addr) {
    asm volatile("ldmatrix.sync.aligned.m8n8.x4.shared.b16 {%0,%1,%2,%3},[%4];"
        : "=r"(a[0]), "=r"(a[1]), "=r"(a[2]), "=r"(a[3]) : "r"(addr));
}
__device__ __forceinline__ void ldsm2t(u32 b[2], u32 addr) {
    asm volatile("ldmatrix.sync.aligned.m8n8.x2.trans.shared.b16 {%0,%1},[%2];"
        : "=r"(b[0]), "=r"(b[1]) : "r"(addr));
}
__device__ __forceinline__ void mma16816(float d[4], const u32 a[4], const u32 b[2]) {
    asm volatile("mma.sync.aligned.m16n8k16.row.col.f32.bf16.bf16.f32 "
        "{%0,%1,%2,%3},{%4,%5,%6,%7},{%8,%9},{%0,%1,%2,%3};"
        : "+f"(d[0]), "+f"(d[1]), "+f"(d[2]), "+f"(d[3])
        : "r"(a[0]), "r"(a[1]), "r"(a[2]), "r"(a[3]), "r"(b[0]), "r"(b[1]));
}
__device__ __forceinline__ void load_w(char* smc, const float* __restrict__ W,
                                       int ldw, int cb, int tid) {
    #pragma unroll
    for (int i = 0; i < 8; ++i) {
        int f = tid + i * TPB;
        int k = f >> 4, j4 = (f & 15) * 4;
        float4 w = *reinterpret_cast<const float4*>(W + (size_t)k * ldw + cb + j4);
        u32 h0, l0, h1, l1;
        split2(w.x, w.y, h0, l0); split2(w.z, w.w, h1, l1);
        char* p = smc + k * WST + j4 * 2;
        *reinterpret_cast<uint2*>(p + OFF_WH) = make_uint2(h0, h1);
        *reinterpret_cast<uint2*>(p + OFF_WL) = make_uint2(l0, l1);
    }
}
__device__ __forceinline__ void gemm_chunk(u32 smb, int lane, int mband, int nhalf,
                                           float d[4][4]) {
    u32 aH = smb + OFF_AH + (mband * 16 + (lane & 15)) * AST + (lane >> 4) * 16;
    u32 aL = aH + (OFF_AL - OFF_AH);
    u32 bRow = smb + OFF_WH + (lane & 15) * WST + nhalf * 64;
    #pragma unroll
    for (int ks = 0; ks < 8; ++ks) {
        u32 ah[4], al[4];
        ldsm4(ah, aH + ks * 32);
        ldsm4(al, aL + ks * 32);
        #pragma unroll
        for (int nt = 0; nt < 4; ++nt) {
            u32 bh[2], bl[2];
            u32 ba = bRow + ks * 16 * WST + nt * 16;
            ldsm2t(bh, ba);
            ldsm2t(bl, ba + (OFF_WL - OFF_WH));
            mma16816(d[nt], ah, bh);
            mma16816(d[nt], ah, bl);
            mma16816(d[nt], al, bh);
        }
    }
}

__global__ __launch_bounds__(TPB, 1)
void swin_mma_kernel(const float* __restrict__ x,
                     const float* __restrict__ ln_g, const float* __restrict__ ln_b,
                     const float* __restrict__ wqkv, const float* __restrict__ bqkv,
                     const float* __restrict__ wout, const float* __restrict__ bout,
                     float* __restrict__ out) {
    extern __shared__ char smc[];
    float* smf = reinterpret_cast<float*>(smc);
    const u32 smb = smem_u32(smc);
    const int tid = threadIdx.x, wid = tid >> 5, lane = tid & 31;
    const int w = blockIdx.x, b = w >> 6, wy = (w >> 3) & 7, wx = w & 7;

    // ---- Phase A: LayerNorm -> split-bf16 X tiles ----
    {
        float4 gg = *reinterpret_cast<const float4*>(&ln_g[lane * 4]);
        float4 bb = *reinterpret_cast<const float4*>(&ln_b[lane * 4]);
        for (int t = wid; t < 49; t += 8) {
            int r = wy * WSZ + t / WSZ, cp = wx * WSZ + t % WSZ;
            const float* xr = x + (size_t)(b * NPIX + r * HIMG + cp) * CDIM;
            float4 v = *reinterpret_cast<const float4*>(&xr[lane * 4]);
            float s = v.x + v.y + v.z + v.w;
            float q = v.x * v.x + v.y * v.y + v.z * v.z + v.w * v.w;
            #pragma unroll
            for (int o = 16; o; o >>= 1) {
                s += __shfl_xor_sync(0xffffffffu, s, o);
                q += __shfl_xor_sync(0xffffffffu, q, o);
            }
            float mu = s * (1.f / 128.f);
            float rs = rsqrtf(q * (1.f / 128.f) - mu * mu + LN_EPS);
            u32 h0, l0, h1, l1;
            split2((v.x - mu) * rs * gg.x + bb.x, (v.y - mu) * rs * gg.y + bb.y, h0, l0);
            split2((v.z - mu) * rs * gg.z + bb.z, (v.w - mu) * rs * gg.w + bb.w, h1, l1);
            char* p = smc + t * AST + lane * 8;
            *reinterpret_cast<uint2*>(p + OFF_AH) = make_uint2(h0, h1);
            *reinterpret_cast<uint2*>(p + OFF_AL) = make_uint2(l0, l1);
        }
    }
    __syncthreads();

    const int mband = wid >> 1, nhalf = wid & 1, tig = lane & 3, g = lane >> 2;

    // ---- Phase B: QKV GEMM, 6 chunks of N=64, D -> S fp32 (+bias) ----
    for (int ch = 0; ch < 6; ++ch) {
        load_w(smc, wqkv, 384, ch * 64, tid);
        __syncthreads();
        float d[4][4] = {};
        gemm_chunk(smb, lane, mband, nhalf, d);
        int R0 = mband * 16 + g, R1 = R0 + 8;
        #pragma unroll
        for (int nt = 0; nt < 4; ++nt) {
            int n = ch * 64 + nhalf * 32 + nt * 8 + 2 * tig;
            float2 bq = *reinterpret_cast<const float2*>(bqkv + n);
            if (R0 < 49)
                *reinterpret_cast<float2*>(&smf[OFF_S / 4 + R0 * SST + n]) =
                    make_float2(d[nt][0] + bq.x, d[nt][1] + bq.y);
            if (R1 < 49)
                *reinterpret_cast<float2*>(&smf[OFF_S / 4 + R1 * SST + n]) =
                    make_float2(d[nt][2] + bq.x, d[nt][3] + bq.y);
        }
        __syncthreads();
    }

    // ---- Phase C: attention, warp = head, lane owns q-tokens {lane, lane+32} ----
    {
        float* S = smf + OFF_S / 4;
        const int head = wid;
        const int qt0 = lane, qt1r = lane + 32;
        const int qt1 = (qt1r < 49) ? qt1r : qt0;       // clamp (stores predicated)
        u64 q0v[8], q1v[8], o0[8] = {}, o1[8] = {};
        const u64* q0p = reinterpret_cast<const u64*>(&S[qt0 * SST + head * 16]);
        const u64* q1p = reinterpret_cast<const u64*>(&S[qt1 * SST + head * 16]);
        #pragma unroll
        for (int j = 0; j < 8; ++j) { q0v[j] = q0p[j]; q1v[j] = q1p[j]; }
        float den0 = 0.f, den1 = 0.f;
        for (int kt = 0; kt < 49; ++kt) {
            const u64* kr = reinterpret_cast<const u64*>(&S[kt * SST + 128 + head * 16]);
            const u64* vr = reinterpret_cast<const u64*>(&S[kt * SST + 256 + head * 16]);
            u64 kv[8], vv[8];
            #pragma unroll
            for (int j = 0; j < 8; ++j) { kv[j] = kr[j]; vv[j] = vr[j]; }  // broadcast LDS
            u64 s0 = 0ull, s1 = 0ull;
            #pragma unroll
            for (int j = 0; j < 8; ++j) { fma2(s0, q0v[j], kv[j]); fma2(s1, q1v[j], kv[j]); }
            float a0, b0, a1, b1;
            upk2(s0, a0, b0); upk2(s1, a1, b1);
            float e0 = fexp((a0 + b0) * SCALE_F);
            float e1 = fexp((a1 + b1) * SCALE_F);
            den0 += e0; den1 += e1;
            u64 e0p = pk2(e0, e0), e1p = pk2(e1, e1);
            #pragma unroll
            for (int j = 0; j < 8; ++j) { fma2(o0[j], e0p, vv[j]); fma2(o1[j], e1p, vv[j]); }
        }
        float inv0 = __frcp_rn(den0), inv1 = __frcp_rn(den1);
        #pragma unroll
        for (int j = 0; j < 8; ++j) {
            float lo, hi, h, l;
            { u32 uh, ul;
              upk2(o0[j], lo, hi);
              split2(lo * inv0, hi * inv0, uh, ul);
              char* p = smc + qt0 * AST + (head * 16 + 2 * j) * 2;
              *reinterpret_cast<u32*>(p + OFF_AH) = uh;
              *reinterpret_cast<u32*>(p + OFF_AL) = ul; }
            if (qt1r < 49) {
              u32 uh, ul;
              upk2(o1[j], h, l);
              split2(h * inv1, l * inv1, uh, ul);
              char* p = smc + qt1r * AST + (head * 16 + 2 * j) * 2;
              *reinterpret_cast<u32*>(p + OFF_AH) = uh;
              *reinterpret_cast<u32*>(p + OFF_AL) = ul;
            }
        }
    }
    __syncthreads();

    // ---- Phase D: out-proj, 2 chunks of N=64, D -> gmem (+bias) ----
    for (int ch = 0; ch < 2; ++ch) {
        load_w(smc, wout, 128, ch * 64, tid);
        __syncthreads();
        float d[4][4] = {};
        gemm_chunk(smb, lane, mband, nhalf, d);
        int R0 = mband * 16 + g, R1 = R0 + 8;
        #pragma unroll
        for (int nt = 0; nt < 4; ++nt) {
            int n = ch * 64 + nhalf * 32 + nt * 8 + 2 * tig;
            float2 bo = *reinterpret_cast<const float2*>(bout + n);
            if (R0 < 49) {
                int r = wy * WSZ + R0 / WSZ, cp = wx * WSZ + R0 % WSZ;
                *reinterpret_cast<float2*>(out + (size_t)(b * NPIX + r * HIMG + cp) * CDIM + n) =
                    make_float2(d[nt][0] + bo.x, d[nt][1] + bo.y);
            }
            if (R1 < 49) {
                int r = wy * WSZ + R1 / WSZ, cp = wx * WSZ + R1 % WSZ;
                *reinterpret_cast<float2*>(out + (size_t)(b * NPIX + r * HIMG + cp) * CDIM + n) =
                    make_float2(d[nt][2] + bo.x, d[nt][3] + bo.y);
            }
        }
        __syncthreads();
    }
}

extern "C" void kernel_launch(void* const* d_in, const int* in_sizes, int n_in,
                              void* d_out, int out_size) {
    const float* x    = (const float*)d_in[0];
    const float* g    = (const float*)d_in[1];
    const float* bt   = (const float*)d_in[2];
    const float* wqkv = (const float*)d_in[3];
    const float* bqkv = (const float*)d_in[4];
    const float* wout = (const float*)d_in[5];
    const float* bout = (const float*)d_in[6];
    float* out = (float*)d_out;
    cudaFuncSetAttribute(swin_mma_kernel,
                         cudaFuncAttributeMaxDynamicSharedMemorySize, SMEM_BYTES);
    swin_mma_kernel<<<4096, TPB, SMEM_BYTES>>>(x, g, bt, wqkv, bqkv, wout, bout, out);
}

// round 9
// speedup vs baseline: 1.9144x; 1.0958x over previous
#include <cuda_runtime.h>
#include <cuda_bf16.h>

using u32 = unsigned int; using u64 = unsigned long long;
#define TPB 512
constexpr int WSZ = 7, HIMG = 56, NPIX = 3136, CDIM = 128;
constexpr float SCALE_F = 0.25f, LN_EPS = 1e-5f;

// smem layout (bytes)
constexpr int AST = 272;                       // A/A2 tile row stride (136 bf16)
constexpr int WST = 144;                       // W tile row stride (72 bf16)
constexpr int OFF_AH = 0, OFF_AL = 17408;      // X / attn-out tiles, 64 rows
constexpr int OFF_WH = 34816, OFF_WL = 53248;  // W chunk tiles, 128 rows
constexpr int OFF_S  = 71680;                  // QKV fp32 [64 rows][386]
constexpr int SST = 386;
constexpr int SMEM_BYTES = OFF_S + 64 * SST * 4;  // 170496

__device__ __forceinline__ u32 smem_u32(const void* p) {
    u32 a; asm("{ .reg .u64 t; cvta.to.shared.u64 t, %1; cvt.u32.u64 %0, t; }" : "=r"(a) : "l"(p));
    return a;
}
__device__ __forceinline__ void split2(float a, float b, u32& hi, u32& lo) {
    __nv_bfloat16 ha = __float2bfloat16(a), hb = __float2bfloat16(b);
    __nv_bfloat16 la = __float2bfloat16(a - __bfloat162float(ha));
    __nv_bfloat16 lb = __float2bfloat16(b - __bfloat162float(hb));
    hi = (u32)__bfloat16_as_ushort(ha) | ((u32)__bfloat16_as_ushort(hb) << 16);
    lo = (u32)__bfloat16_as_ushort(la) | ((u32)__bfloat16_as_ushort(lb) << 16);
}
__device__ __forceinline__ u64 pk2(float lo, float hi) {
    u64 r; asm("mov.b64 %0,{%1,%2};" : "=l"(r) : "f"(lo), "f"(hi)); return r;
}
__device__ __forceinline__ void fma2(u64& d, u64 a, u64 b) {
    asm("fma.rn.f32x2 %0,%1,%2,%3;" : "=l"(d) : "l"(a), "l"(b), "l"(d));
}
__device__ __forceinline__ void upk2(u64 v, float& lo, float& hi) {
    asm("mov.b64 {%0,%1},%2;" : "=f"(lo), "=f"(hi) : "l"(v));
}
// MUFU-free e^x on FMA/ALU pipes
__device__ __forceinline__ float fexp(float x) {
    float y = fminf(fmaxf(x * 1.44269504f, -126.f), 126.f);
    int ni = __float2int_rn(y);
    float f = y - (float)ni;
    float p = 1.33336e-3f;
    p = fmaf(p, f, 9.61813e-3f);
    p = fmaf(p, f, 5.550411e-2f);
    p = fmaf(p, f, 2.4022651e-1f);
    p = fmaf(p, f, 6.9314718e-1f);
    p = fmaf(p, f, 1.0f);
    return p * __int_as_float((ni + 127) << 23);
}
__device__ __forceinline__ void ldsm4(u32 a[4], u32 addr) {
    asm volatile("ldmatrix.sync.aligned.m8n8.x4.shared.b16 {%0,%1,%2,%3},[%4];"
        : "=r"(a[0]), "=r"(a[1]), "=r"(a[2]), "=r"(a[3]) : "r"(addr));
}
__device__ __forceinline__ void ldsm2t(u32 b[2], u32 addr) {
    asm volatile("ldmatrix.sync.aligned.m8n8.x2.trans.shared.b16 {%0,%1},[%2];"
        : "=r"(b[0]), "=r"(b[1]) : "r"(addr));
}
__device__ __forceinline__ void mma16816(float d[4], const u32 a[4], const u32 b[2]) {
    asm volatile("mma.sync.aligned.m16n8k16.row.col.f32.bf16.bf16.f32 "
        "{%0,%1,%2,%3},{%4,%5,%6,%7},{%8,%9},{%0,%1,%2,%3};"
        : "+f"(d[0]), "+f"(d[1]), "+f"(d[2]), "+f"(d[3])
        : "r"(a[0]), "r"(a[1]), "r"(a[2]), "r"(a[3]), "r"(b[0]), "r"(b[1]));
}
__device__ __forceinline__ void load_w(char* smc, const float* __restrict__ W,
                                       int ldw, int cb, int tid) {
    #pragma unroll
    for (int i = 0; i < 4; ++i) {
        int f = tid + i * TPB;            // 0..2047
        int k = f >> 4, j4 = (f & 15) * 4;
        float4 w = *reinterpret_cast<const float4*>(W + (size_t)k * ldw + cb + j4);
        u32 h0, l0, h1, l1;
        split2(w.x, w.y, h0, l0); split2(w.z, w.w, h1, l1);
        char* p = smc + k * WST + j4 * 2;
        *reinterpret_cast<uint2*>(p + OFF_WH) = make_uint2(h0, h1);
        *reinterpret_cast<uint2*>(p + OFF_WL) = make_uint2(l0, l1);
    }
}
// C[64x64] chunk; 16 warps, warp tile = 16 rows x 16 cols
__device__ __forceinline__ void gemm_chunk(u32 smb, int lane, int mband, int nq,
                                           float d[2][4]) {
    u32 aH = smb + OFF_AH + (mband * 16 + (lane & 15)) * AST + (lane >> 4) * 16;
    u32 aL = aH + (OFF_AL - OFF_AH);
    u32 bRow = smb + OFF_WH + (lane & 15) * WST + nq * 32;
    #pragma unroll
    for (int ks = 0; ks < 8; ++ks) {
        u32 ah[4], al[4];
        ldsm4(ah, aH + ks * 32);
        ldsm4(al, aL + ks * 32);
        #pragma unroll
        for (int nt = 0; nt < 2; ++nt) {
            u32 bh[2], bl[2];
            u32 ba = bRow + ks * 16 * WST + nt * 16;
            ldsm2t(bh, ba);
            ldsm2t(bl, ba + (OFF_WL - OFF_WH));
            mma16816(d[nt], ah, bh);
            mma16816(d[nt], ah, bl);
            mma16816(d[nt], al, bh);
        }
    }
}

__global__ __launch_bounds__(TPB, 1)
void swin_mma_kernel(const float* __restrict__ x,
                     const float* __restrict__ ln_g, const float* __restrict__ ln_b,
                     const float* __restrict__ wqkv, const float* __restrict__ bqkv,
                     const float* __restrict__ wout, const float* __restrict__ bout,
                     float* __restrict__ out) {
    extern __shared__ char smc[];
    float* smf = reinterpret_cast<float*>(smc);
    const u32 smb = smem_u32(smc);
    const int tid = threadIdx.x, wid = tid >> 5, lane = tid & 31;
    const int w = blockIdx.x, b = w >> 6, wy = (w >> 3) & 7, wx = w & 7;

    // ---- Phase A: LayerNorm -> split-bf16 X tiles ----
    {
        float4 gg = *reinterpret_cast<const float4*>(&ln_g[lane * 4]);
        float4 bb = *reinterpret_cast<const float4*>(&ln_b[lane * 4]);
        for (int t = wid; t < 49; t += 16) {
            int r = wy * WSZ + t / WSZ, cp = wx * WSZ + t % WSZ;
            const float* xr = x + (size_t)(b * NPIX + r * HIMG + cp) * CDIM;
            float4 v = *reinterpret_cast<const float4*>(&xr[lane * 4]);
            float s = v.x + v.y + v.z + v.w;
            float q = v.x * v.x + v.y * v.y + v.z * v.z + v.w * v.w;
            #pragma unroll
            for (int o = 16; o; o >>= 1) {
                s += __shfl_xor_sync(0xffffffffu, s, o);
                q += __shfl_xor_sync(0xffffffffu, q, o);
            }
            float mu = s * (1.f / 128.f);
            float rs = rsqrtf(q * (1.f / 128.f) - mu * mu + LN_EPS);
            u32 h0, l0, h1, l1;
            split2((v.x - mu) * rs * gg.x + bb.x, (v.y - mu) * rs * gg.y + bb.y, h0, l0);
            split2((v.z - mu) * rs * gg.z + bb.z, (v.w - mu) * rs * gg.w + bb.w, h1, l1);
            char* p = smc + t * AST + lane * 8;
            *reinterpret_cast<uint2*>(p + OFF_AH) = make_uint2(h0, h1);
            *reinterpret_cast<uint2*>(p + OFF_AL) = make_uint2(l0, l1);
        }
    }
    __syncthreads();

    const int mband = wid >> 2, nq = wid & 3, tig = lane & 3, g = lane >> 2;

    // ---- Phase B: QKV GEMM, 6 chunks of N=64, D -> S fp32 (+bias) ----
    for (int ch = 0; ch < 6; ++ch) {
        load_w(smc, wqkv, 384, ch * 64, tid);
        __syncthreads();
        float d[2][4] = {};
        gemm_chunk(smb, lane, mband, nq, d);
        int R0 = mband * 16 + g, R1 = R0 + 8;
        #pragma unroll
        for (int nt = 0; nt < 2; ++nt) {
            int n = ch * 64 + nq * 16 + nt * 8 + 2 * tig;
            float2 bq = *reinterpret_cast<const float2*>(bqkv + n);
            if (R0 < 49)
                *reinterpret_cast<float2*>(&smf[OFF_S / 4 + R0 * SST + n]) =
                    make_float2(d[nt][0] + bq.x, d[nt][1] + bq.y);
            if (R1 < 49)
                *reinterpret_cast<float2*>(&smf[OFF_S / 4 + R1 * SST + n]) =
                    make_float2(d[nt][2] + bq.x, d[nt][3] + bq.y);
        }
        __syncthreads();
    }

    // ---- Phase C: attention; 2 warps per head, lane owns ONE q-token ----
    {
        float* S = smf + OFF_S / 4;
        const int head = wid & 7, half = wid >> 3;
        const int qtr = half * 32 + lane;
        const bool act = qtr < 49;
        const int qt = act ? qtr : 0;
        u64 qv[8], o[8] = {};
        const u64* qp = reinterpret_cast<const u64*>(&S[qt * SST + head * 16]);
        #pragma unroll
        for (int j = 0; j < 8; ++j) qv[j] = qp[j];
        float den = 0.f;
        for (int kt = 0; kt < 49; ++kt) {
            const u64* kr = reinterpret_cast<const u64*>(&S[kt * SST + 128 + head * 16]);
            const u64* vr = reinterpret_cast<const u64*>(&S[kt * SST + 256 + head * 16]);
            u64 kv[8], vv[8];
            #pragma unroll
            for (int j = 0; j < 8; ++j) { kv[j] = kr[j]; vv[j] = vr[j]; }  // broadcast LDS
            u64 s2 = 0ull;
            #pragma unroll
            for (int j = 0; j < 8; ++j) fma2(s2, qv[j], kv[j]);
            float sa, sb;
            upk2(s2, sa, sb);
            float e = fexp((sa + sb) * SCALE_F);
            den += e;
            u64 ep = pk2(e, e);
            #pragma unroll
            for (int j = 0; j < 8; ++j) fma2(o[j], ep, vv[j]);
        }
        float inv = __frcp_rn(den);
        if (act) {
            #pragma unroll
            for (int j = 0; j < 8; ++j) {
                float lo, hi; u32 uh, ul;
                upk2(o[j], lo, hi);
                split2(lo * inv, hi * inv, uh, ul);
                char* p = smc + qtr * AST + (head * 16 + 2 * j) * 2;
                *reinterpret_cast<u32*>(p + OFF_AH) = uh;
                *reinterpret_cast<u32*>(p + OFF_AL) = ul;
            }
        }
    }
    __syncthreads();

    // ---- Phase D: out-proj, 2 chunks of N=64, D -> gmem (+bias) ----
    for (int ch = 0; ch < 2; ++ch) {
        load_w(smc, wout, 128, ch * 64, tid);
        __syncthreads();
        float d[2][4] = {};
        gemm_chunk(smb, lane, mband, nq, d);
        int R0 = mband * 16 + g, R1 = R0 + 8;
        #pragma unroll
        for (int nt = 0; nt < 2; ++nt) {
            int n = ch * 64 + nq * 16 + nt * 8 + 2 * tig;
            float2 bo = *reinterpret_cast<const float2*>(bout + n);
            if (R0 < 49) {
                int r = wy * WSZ + R0 / WSZ, cp = wx * WSZ + R0 % WSZ;
                *reinterpret_cast<float2*>(out + (size_t)(b * NPIX + r * HIMG + cp) * CDIM + n) =
                    make_float2(d[nt][0] + bo.x, d[nt][1] + bo.y);
            }
            if (R1 < 49) {
                int r = wy * WSZ + R1 / WSZ, cp = wx * WSZ + R1 % WSZ;
                *reinterpret_cast<float2*>(out + (size_t)(b * NPIX + r * HIMG + cp) * CDIM + n) =
                    make_float2(d[nt][2] + bo.x, d[nt][3] + bo.y);
            }
        }
        __syncthreads();
    }
}

extern "C" void kernel_launch(void* const* d_in, const int* in_sizes, int n_in,
                              void* d_out, int out_size) {
    const float* x    = (const float*)d_in[0];
    const float* g    = (const float*)d_in[1];
    const float* bt   = (const float*)d_in[2];
    const float* wqkv = (const float*)d_in[3];
    const float* bqkv = (const float*)d_in[4];
    const float* wout = (const float*)d_in[5];
    const float* bout = (const float*)d_in[6];
    float* out = (float*)d_out;
    cudaFuncSetAttribute(swin_mma_kernel,
                         cudaFuncAttributeMaxDynamicSharedMemorySize, SMEM_BYTES);
    swin_mma_kernel<<<4096, TPB, SMEM_BYTES>>>(x, g, bt, wqkv, bqkv, wout, bout, out);
}

// round 13
// speedup vs baseline: 2.1214x; 1.1081x over previous
#include <cuda_runtime.h>
#include <cuda_bf16.h>

using u32 = unsigned int; using u64 = unsigned long long;
#define TPB 512
constexpr int WSZ = 7, HIMG = 56, NPIX = 3136, CDIM = 128;
constexpr float SCALE_F = 0.25f, LN_EPS = 1e-5f;

// smem layout (bytes)
constexpr int AST = 272;                      // tile row stride (136 bf16)
constexpr int WST = 144;                      // W tile row stride
constexpr int TILE = 17408;                   // one 64-row tile (64*AST)
constexpr int OFF_XH = 0, OFF_XL = TILE;      // X tiles; reused as attn-out A2
constexpr int OFF_WH = 34816, OFF_WL = 53248; // W chunk tiles, 128 rows
constexpr int OFF_Q = 71680;                  // Qh,Ql,Kh,Kl,Vh,Vl tiles (6 x TILE)
constexpr int OFF_K = OFF_Q + 2 * TILE;
constexpr int OFF_V = OFF_Q + 4 * TILE;
constexpr int SMEM_BYTES = OFF_Q + 6 * TILE;  // 176128

__device__ __forceinline__ u32 smem_u32(const void* p) {
    u32 a; asm("{ .reg .u64 t; cvta.to.shared.u64 t, %1; cvt.u32.u64 %0, t; }" : "=r"(a) : "l"(p));
    return a;
}
__device__ __forceinline__ void split2(float a, float b, u32& hi, u32& lo) {
    __nv_bfloat16 ha = __float2bfloat16(a), hb = __float2bfloat16(b);
    __nv_bfloat16 la = __float2bfloat16(a - __bfloat162float(ha));
    __nv_bfloat16 lb = __float2bfloat16(b - __bfloat162float(hb));
    hi = (u32)__bfloat16_as_ushort(ha) | ((u32)__bfloat16_as_ushort(hb) << 16);
    lo = (u32)__bfloat16_as_ushort(la) | ((u32)__bfloat16_as_ushort(lb) << 16);
}
// MUFU-free e^x (FMA/ALU pipes); NaN/garbage clamps to tiny, never Inf/NaN out
__device__ __forceinline__ float fexp(float x) {
    float y = fminf(fmaxf(x * 1.44269504f, -126.f), 126.f);
    int ni = __float2int_rn(y);
    float f = y - (float)ni;
    float p = 1.33336e-3f;
    p = fmaf(p, f, 9.61813e-3f);
    p = fmaf(p, f, 5.550411e-2f);
    p = fmaf(p, f, 2.4022651e-1f);
    p = fmaf(p, f, 6.9314718e-1f);
    p = fmaf(p, f, 1.0f);
    return p * __int_as_float((ni + 127) << 23);
}
__device__ __forceinline__ void ldsm4(u32 a[4], u32 addr) {
    asm volatile("ldmatrix.sync.aligned.m8n8.x4.shared.b16 {%0,%1,%2,%3},[%4];"
        : "=r"(a[0]), "=r"(a[1]), "=r"(a[2]), "=r"(a[3]) : "r"(addr));
}
__device__ __forceinline__ void ldsm2t(u32 b[2], u32 addr) {
    asm volatile("ldmatrix.sync.aligned.m8n8.x2.trans.shared.b16 {%0,%1},[%2];"
        : "=r"(b[0]), "=r"(b[1]) : "r"(addr));
}
__device__ __forceinline__ void ldsm2(u32 b[2], u32 addr) {
    asm volatile("ldmatrix.sync.aligned.m8n8.x2.shared.b16 {%0,%1},[%2];"
        : "=r"(b[0]), "=r"(b[1]) : "r"(addr));
}
__device__ __forceinline__ void mma16816(float d[4], const u32 a[4], const u32 b[2]) {
    asm volatile("mma.sync.aligned.m16n8k16.row.col.f32.bf16.bf16.f32 "
        "{%0,%1,%2,%3},{%4,%5,%6,%7},{%8,%9},{%0,%1,%2,%3};"
        : "+f"(d[0]), "+f"(d[1]), "+f"(d[2]), "+f"(d[3])
        : "r"(a[0]), "r"(a[1]), "r"(a[2]), "r"(a[3]), "r"(b[0]), "r"(b[1]));
}
__device__ __forceinline__ void load_w(char* smc, const float* __restrict__ W,
                                       int ldw, int cb, int tid) {
    #pragma unroll
    for (int i = 0; i < 4; ++i) {
        int f = tid + i * TPB;
        int k = f >> 4, j4 = (f & 15) * 4;
        float4 w = *reinterpret_cast<const float4*>(W + (size_t)k * ldw + cb + j4);
        u32 h0, l0, h1, l1;
        split2(w.x, w.y, h0, l0); split2(w.z, w.w, h1, l1);
        char* p = smc + k * WST + j4 * 2;
        *reinterpret_cast<uint2*>(p + OFF_WH) = make_uint2(h0, h1);
        *reinterpret_cast<uint2*>(p + OFF_WL) = make_uint2(l0, l1);
    }
}
// C[64x64] chunk; 16 warps, warp tile 16x16; A tiles at OFF_XH/OFF_XL
__device__ __forceinline__ void gemm_chunk(u32 smb, int lane, int mband, int nq,
                                           float d[2][4]) {
    u32 aH = smb + OFF_XH + (mband * 16 + (lane & 15)) * AST + (lane >> 4) * 16;
    u32 bRow = smb + OFF_WH + (lane & 15) * WST + nq * 32;
    #pragma unroll
    for (int ks = 0; ks < 8; ++ks) {
        u32 ah[4], al[4];
        ldsm4(ah, aH + ks * 32);
        ldsm4(al, aH + ks * 32 + TILE);
        #pragma unroll
        for (int nt = 0; nt < 2; ++nt) {
            u32 bh[2], bl[2];
            u32 ba = bRow + ks * 16 * WST + nt * 16;
            ldsm2t(bh, ba);
            ldsm2t(bl, ba + (OFF_WL - OFF_WH));
            mma16816(d[nt], ah, bh);
            mma16816(d[nt], ah, bl);
            mma16816(d[nt], al, bh);
        }
    }
}

__global__ __launch_bounds__(TPB, 1)
void swin_mma_kernel(const float* __restrict__ x,
                     const float* __restrict__ ln_g, const float* __restrict__ ln_b,
                     const float* __restrict__ wqkv, const float* __restrict__ bqkv,
                     const float* __restrict__ wout, const float* __restrict__ bout,
                     float* __restrict__ out) {
    extern __shared__ char smc[];
    const u32 smb = smem_u32(smc);
    const int tid = threadIdx.x, wid = tid >> 5, lane = tid & 31;
    const int w = blockIdx.x, b = w >> 6, wy = (w >> 3) & 7, wx = w & 7;

    // zero V-tile pad rows 49..63 (prevents 0*NaN poison in PV mma)
    if (tid < 480) {
        int t = tid, tile = t / 240, rem = t % 240;
        int row = 49 + rem / 16, q16 = (rem & 15) * 16;
        *reinterpret_cast<uint4*>(smc + OFF_V + tile * TILE + row * AST + q16) =
            make_uint4(0, 0, 0, 0);
    }

    // ---- Phase A: LayerNorm -> split-bf16 X tiles ----
    {
        float4 gg = *reinterpret_cast<const float4*>(&ln_g[lane * 4]);
        float4 bb = *reinterpret_cast<const float4*>(&ln_b[lane * 4]);
        for (int t = wid; t < 49; t += 16) {
            int r = wy * WSZ + t / WSZ, cp = wx * WSZ + t % WSZ;
            const float* xr = x + (size_t)(b * NPIX + r * HIMG + cp) * CDIM;
            float4 v = *reinterpret_cast<const float4*>(&xr[lane * 4]);
            float s = v.x + v.y + v.z + v.w;
            float q = v.x * v.x + v.y * v.y + v.z * v.z + v.w * v.w;
            #pragma unroll
            for (int o = 16; o; o >>= 1) {
                s += __shfl_xor_sync(0xffffffffu, s, o);
                q += __shfl_xor_sync(0xffffffffu, q, o);
            }
            float mu = s * (1.f / 128.f);
            float rs = rsqrtf(q * (1.f / 128.f) - mu * mu + LN_EPS);
            u32 h0, l0, h1, l1;
            split2((v.x - mu) * rs * gg.x + bb.x, (v.y - mu) * rs * gg.y + bb.y, h0, l0);
            split2((v.z - mu) * rs * gg.z + bb.z, (v.w - mu) * rs * gg.w + bb.w, h1, l1);
            char* p = smc + t * AST + lane * 8;
            *reinterpret_cast<uint2*>(p + OFF_XH) = make_uint2(h0, h1);
            *reinterpret_cast<uint2*>(p + OFF_XL) = make_uint2(l0, l1);
        }
    }
    __syncthreads();

    const int mband = wid >> 2, nq = wid & 3, tig = lane & 3, g = lane >> 2;

    // ---- Phase B: QKV GEMM, 6 chunks of N=64 -> split-bf16 Q/K/V tiles (+bias) ----
    for (int ch = 0; ch < 6; ++ch) {
        load_w(smc, wqkv, 384, ch * 64, tid);
        __syncthreads();
        float d[2][4] = {};
        gemm_chunk(smb, lane, mband, nq, d);
        int R0 = mband * 16 + g, R1 = R0 + 8;
        #pragma unroll
        for (int nt = 0; nt < 2; ++nt) {
            int n = ch * 64 + nq * 16 + nt * 8 + 2 * tig;
            int base = OFF_Q + (n >> 7) * 2 * TILE, col = n & 127;
            float2 bq = *reinterpret_cast<const float2*>(bqkv + n);
            if (R0 < 49) {
                u32 uh, ul;
                split2(d[nt][0] + bq.x, d[nt][1] + bq.y, uh, ul);
                char* p = smc + base + R0 * AST + col * 2;
                *reinterpret_cast<u32*>(p) = uh;
                *reinterpret_cast<u32*>(p + TILE) = ul;
            }
            if (R1 < 49) {
                u32 uh, ul;
                split2(d[nt][2] + bq.x, d[nt][3] + bq.y, uh, ul);
                char* p = smc + base + R1 * AST + col * 2;
                *reinterpret_cast<u32*>(p) = uh;
                *reinterpret_cast<u32*>(p + TILE) = ul;
            }
        }
        __syncthreads();
    }

    // ---- Phase C: tensor-core attention; warp = (head, 2 q-bands) ----
    {
        const int head = wid & 7, half = wid >> 3;
        #pragma unroll
        for (int band = 0; band < 2; ++band) {
            int m0 = (half * 2 + band) * 16;
            u32 qh[4], ql[4];
            u32 aaddr = smb + OFF_Q + (m0 + (lane & 15)) * AST + head * 32 + (lane >> 4) * 16;
            ldsm4(qh, aaddr);
            ldsm4(ql, aaddr + TILE);
            // S = Q K^T (3-term split); B via NON-trans ldsm on K rows [n=kt][k=d]
            float sd[7][4];
            #pragma unroll
            for (int nt = 0; nt < 7; ++nt) { sd[nt][0]=sd[nt][1]=sd[nt][2]=sd[nt][3]=0.f; }
            u32 baddr = smb + OFF_K + (lane & 7) * AST + head * 32 + ((lane >> 3) & 1) * 16;
            #pragma unroll
            for (int nt = 0; nt < 7; ++nt) {
                u32 bh[2], bl[2];
                ldsm2(bh, baddr + nt * 8 * AST);
                ldsm2(bl, baddr + nt * 8 * AST + TILE);
                mma16816(sd[nt], qh, bh);
                mma16816(sd[nt], qh, bl);
                mma16816(sd[nt], ql, bh);
            }
            // softmax (unnormalized); mask cols >= 49; split e -> bf16 P pairs
            float den0 = 0.f, den1 = 0.f;
            u32 Phg[8], Phg8[8], Plg[8], Plg8[8];
            #pragma unroll
            for (int nt = 0; nt < 7; ++nt) {
                float e0 = fexp(sd[nt][0] * SCALE_F);
                float e1 = fexp(sd[nt][1] * SCALE_F);
                float e2 = fexp(sd[nt][2] * SCALE_F);
                float e3 = fexp(sd[nt][3] * SCALE_F);
                if (nt == 6) {
                    bool v0 = (48 + 2 * tig) < 49;   // only tig==0 col 48 valid
                    e0 = v0 ? e0 : 0.f; e2 = v0 ? e2 : 0.f;
                    e1 = 0.f; e3 = 0.f;
                }
                den0 += e0 + e1; den1 += e2 + e3;
                split2(e0, e1, Phg[nt], Plg[nt]);
                split2(e2, e3, Phg8[nt], Plg8[nt]);
            }
            Phg[7] = Plg[7] = Phg8[7] = Plg8[7] = 0u;
            den0 += __shfl_xor_sync(0xffffffffu, den0, 1);
            den0 += __shfl_xor_sync(0xffffffffu, den0, 2);
            den1 += __shfl_xor_sync(0xffffffffu, den1, 1);
            den1 += __shfl_xor_sync(0xffffffffu, den1, 2);
            // O = P V (3-term split); normalize after
            float od[2][4] = {};
            #pragma unroll
            for (int kc = 0; kc < 4; ++kc) {
                u32 ah[4] = {Phg[2*kc], Phg8[2*kc], Phg[2*kc+1], Phg8[2*kc+1]};
                u32 al[4] = {Plg[2*kc], Plg8[2*kc], Plg[2*kc+1], Plg8[2*kc+1]};
                u32 vaddr = smb + OFF_V + (kc * 16 + (lane & 15)) * AST + head * 32;
                #pragma unroll
                for (int ntO = 0; ntO < 2; ++ntO) {
                    u32 vh[2], vl[2];
                    ldsm2t(vh, vaddr + ntO * 16);
                    ldsm2t(vl, vaddr + ntO * 16 + TILE);
                    mma16816(od[ntO], ah, vh);
                    mma16816(od[ntO], ah, vl);
                    mma16816(od[ntO], al, vh);
                }
            }
            float inv0 = __frcp_rn(den0), inv1 = __frcp_rn(den1);
            int r0 = m0 + g, r1 = r0 + 8;
            #pragma unroll
            for (int ntO = 0; ntO < 2; ++ntO) {
                int col = head * 16 + ntO * 8 + 2 * tig;
                if (r0 < 49) {
                    u32 uh, ul;
                    split2(od[ntO][0] * inv0, od[ntO][1] * inv0, uh, ul);
                    char* p = smc + r0 * AST + col * 2;
                    *reinterpret_cast<u32*>(p + OFF_XH) = uh;
                    *reinterpret_cast<u32*>(p + OFF_XL) = ul;
                }
                if (r1 < 49) {
                    u32 uh, ul;
                    split2(od[ntO][2] * inv1, od[ntO][3] * inv1, uh, ul);
                    char* p = smc + r1 * AST + col * 2;
                    *reinterpret_cast<u32*>(p + OFF_XH) = uh;
                    *reinterpret_cast<u32*>(p + OFF_XL) = ul;
                }
            }
        }
    }
    __syncthreads();

    // ---- Phase D: out-proj, 2 chunks of N=64, D -> gmem (+bias) ----
    for (int ch = 0; ch < 2; ++ch) {
        load_w(smc, wout, 128, ch * 64, tid);
        __syncthreads();
        float d[2][4] = {};
        gemm_chunk(smb, lane, mband, nq, d);
        int R0 = mband * 16 + g, R1 = R0 + 8;
        #pragma unroll
        for (int nt = 0; nt < 2; ++nt) {
            int n = ch * 64 + nq * 16 + nt * 8 + 2 * tig;
            float2 bo = *reinterpret_cast<const float2*>(bout + n);
            if (R0 < 49) {
                int r = wy * WSZ + R0 / WSZ, cp = wx * WSZ + R0 % WSZ;
                *reinterpret_cast<float2*>(out + (size_t)(b * NPIX + r * HIMG + cp) * CDIM + n) =
                    make_float2(d[nt][0] + bo.x, d[nt][1] + bo.y);
            }
            if (R1 < 49) {
                int r = wy * WSZ + R1 / WSZ, cp = wx * WSZ + R1 % WSZ;
                *reinterpret_cast<float2*>(out + (size_t)(b * NPIX + r * HIMG + cp) * CDIM + n) =
                    make_float2(d[nt][2] + bo.x, d[nt][3] + bo.y);
            }
        }
        __syncthreads();
    }
}

extern "C" void kernel_launch(void* const* d_in, const int* in_sizes, int n_in,
                              void* d_out, int out_size) {
    const float* x    = (const float*)d_in[0];
    const float* g    = (const float*)d_in[1];
    const float* bt   = (const float*)d_in[2];
    const float* wqkv = (const float*)d_in[3];
    const float* bqkv = (const float*)d_in[4];
    const float* wout = (const float*)d_in[5];
    const float* bout = (const float*)d_in[6];
    float* out = (float*)d_out;
    cudaFuncSetAttribute(swin_mma_kernel,
                         cudaFuncAttributeMaxDynamicSharedMemorySize, SMEM_BYTES);
    swin_mma_kernel<<<4096, TPB, SMEM_BYTES>>>(x, g, bt, wqkv, bqkv, wout, bout, out);
}

// round 14
// speedup vs baseline: 2.4175x; 1.1396x over previous
#include <cuda_runtime.h>
#include <cuda_bf16.h>

using u32 = unsigned int; using u64 = unsigned long long;
#define TPB 512
constexpr int WSZ = 7, HIMG = 56, NPIX = 3136, CDIM = 128;
constexpr float SCALE_F = 0.25f, LN_EPS = 1e-5f;

// smem layout (bytes)
constexpr int AST = 272;                      // tile row stride (136 bf16)
constexpr int WST = 144;                      // W tile row stride
constexpr int TILE = 17408;                   // one 64-row tile
constexpr int OFF_XH = 0, OFF_XL = TILE;      // X tiles; reused as attn-out A2
constexpr int WBUFSZ = 36864;                 // hi plane + lo plane (18432 each)
constexpr int OFF_W0 = 34816;                 // W double buffers
constexpr int WLO = 18432;                    // lo-plane offset within a W buffer
constexpr int OFF_Q = 108544;                 // Qh,Ql,Kh,Kl,Vh,Vl tiles
constexpr int OFF_K = OFF_Q + 2 * TILE;
constexpr int OFF_V = OFF_Q + 4 * TILE;
constexpr int SMEM_BYTES = OFF_Q + 6 * TILE;  // 212992

// precomputed split-bf16 weights (written by prep kernel)
__device__ __nv_bfloat16 d_wqH[49152], d_wqL[49152], d_woH[16384], d_woL[16384];

__global__ void prep_w_kernel(const float* __restrict__ wqkv, const float* __restrict__ wout) {
    int i = blockIdx.x * 256 + threadIdx.x;
    if (i < 49152) {
        float v = wqkv[i];
        __nv_bfloat16 h = __float2bfloat16(v);
        d_wqH[i] = h; d_wqL[i] = __float2bfloat16(v - __bfloat162float(h));
    } else {
        int j = i - 49152;
        float v = wout[j];
        __nv_bfloat16 h = __float2bfloat16(v);
        d_woH[j] = h; d_woL[j] = __float2bfloat16(v - __bfloat162float(h));
    }
}

__device__ __forceinline__ u32 smem_u32(const void* p) {
    u32 a; asm("{ .reg .u64 t; cvta.to.shared.u64 t, %1; cvt.u32.u64 %0, t; }" : "=r"(a) : "l"(p));
    return a;
}
__device__ __forceinline__ u64 gaddr(const void* p) {
    u64 g; asm("cvta.to.global.u64 %0, %1;" : "=l"(g) : "l"(p)); return g;
}
#define CP16(d, s)   asm volatile("cp.async.cg.shared.global [%0], [%1], 16;" :: "r"(d), "l"(s) : "memory")
#define CP_COMMIT()  asm volatile("cp.async.commit_group;" ::: "memory")
#define CP_WAIT(N)   asm volatile("cp.async.wait_group %0;" :: "n"(N) : "memory")

__device__ __forceinline__ void split2(float a, float b, u32& hi, u32& lo) {
    __nv_bfloat16 ha = __float2bfloat16(a), hb = __float2bfloat16(b);
    __nv_bfloat16 la = __float2bfloat16(a - __bfloat162float(ha));
    __nv_bfloat16 lb = __float2bfloat16(b - __bfloat162float(hb));
    hi = (u32)__bfloat16_as_ushort(ha) | ((u32)__bfloat16_as_ushort(hb) << 16);
    lo = (u32)__bfloat16_as_ushort(la) | ((u32)__bfloat16_as_ushort(lb) << 16);
}
// MUFU-free e^x
__device__ __forceinline__ float fexp(float x) {
    float y = fminf(fmaxf(x * 1.44269504f, -126.f), 126.f);
    int ni = __float2int_rn(y);
    float f = y - (float)ni;
    float p = 1.33336e-3f;
    p = fmaf(p, f, 9.61813e-3f);
    p = fmaf(p, f, 5.550411e-2f);
    p = fmaf(p, f, 2.4022651e-1f);
    p = fmaf(p, f, 6.9314718e-1f);
    p = fmaf(p, f, 1.0f);
    return p * __int_as_float((ni + 127) << 23);
}
__device__ __forceinline__ void ldsm4(u32 a[4], u32 addr) {
    asm volatile("ldmatrix.sync.aligned.m8n8.x4.shared.b16 {%0,%1,%2,%3},[%4];"
        : "=r"(a[0]), "=r"(a[1]), "=r"(a[2]), "=r"(a[3]) : "r"(addr));
}
__device__ __forceinline__ void ldsm2t(u32 b[2], u32 addr) {
    asm volatile("ldmatrix.sync.aligned.m8n8.x2.trans.shared.b16 {%0,%1},[%2];"
        : "=r"(b[0]), "=r"(b[1]) : "r"(addr));
}
__device__ __forceinline__ void ldsm2(u32 b[2], u32 addr) {
    asm volatile("ldmatrix.sync.aligned.m8n8.x2.shared.b16 {%0,%1},[%2];"
        : "=r"(b[0]), "=r"(b[1]) : "r"(addr));
}
__device__ __forceinline__ void mma16816(float d[4], const u32 a[4], const u32 b[2]) {
    asm volatile("mma.sync.aligned.m16n8k16.row.col.f32.bf16.bf16.f32 "
        "{%0,%1,%2,%3},{%4,%5,%6,%7},{%8,%9},{%0,%1,%2,%3};"
        : "+f"(d[0]), "+f"(d[1]), "+f"(d[2]), "+f"(d[3])
        : "r"(a[0]), "r"(a[1]), "r"(a[2]), "r"(a[3]), "r"(b[0]), "r"(b[1]));
}
// async-copy one W chunk [128k x 64n] (hi+lo planes) into smem buffer
__device__ __forceinline__ void cp_w(u32 wbase, const __nv_bfloat16* Hp, const __nv_bfloat16* Lp,
                                     int ldw, int cb, int tid) {
    #pragma unroll
    for (int i = 0; i < 2; ++i) {
        int f = tid + i * TPB;             // 0..1023
        int k = f >> 3, n8 = f & 7;
        u32 dst = wbase + k * WST + n8 * 16;
        CP16(dst, gaddr(Hp + k * ldw + cb + n8 * 8));
        CP16(dst + WLO, gaddr(Lp + k * ldw + cb + n8 * 8));
    }
}
// C[64x64] chunk; 16 warps, warp tile 16x16; A tiles at OFF_XH/OFF_XL
__device__ __forceinline__ void gemm_chunk(u32 smb, u32 wbase, int lane, int mband, int nq,
                                           float d[2][4]) {
    u32 aH = smb + OFF_XH + (mband * 16 + (lane & 15)) * AST + (lane >> 4) * 16;
    u32 bRow = wbase + (lane & 15) * WST + nq * 32;
    #pragma unroll
    for (int ks = 0; ks < 8; ++ks) {
        u32 ah[4], al[4];
        ldsm4(ah, aH + ks * 32);
        ldsm4(al, aH + ks * 32 + TILE);
        #pragma unroll
        for (int nt = 0; nt < 2; ++nt) {
            u32 bh[2], bl[2];
            u32 ba = bRow + ks * 16 * WST + nt * 16;
            ldsm2t(bh, ba);
            ldsm2t(bl, ba + WLO);
            mma16816(d[nt], ah, bh);
            mma16816(d[nt], ah, bl);
            mma16816(d[nt], al, bh);
        }
    }
}

__global__ __launch_bounds__(TPB, 1)
void swin_mma_kernel(const float* __restrict__ x,
                     const float* __restrict__ ln_g, const float* __restrict__ ln_b,
                     const float* __restrict__ bqkv, const float* __restrict__ bout,
                     float* __restrict__ out) {
    extern __shared__ char smc[];
    const u32 smb = smem_u32(smc);
    const int tid = threadIdx.x, wid = tid >> 5, lane = tid & 31;
    const int w = blockIdx.x, b = w >> 6, wy = (w >> 3) & 7, wx = w & 7;

    // prefetch W chunks 0,1 (overlaps LN below)
    cp_w(smb + OFF_W0,          d_wqH, d_wqL, 384, 0,  tid); CP_COMMIT();
    cp_w(smb + OFF_W0 + WBUFSZ, d_wqH, d_wqL, 384, 64, tid); CP_COMMIT();

    // zero V-tile pad rows 49..63
    if (tid < 480) {
        int t = tid, tile = t / 240, rem = t % 240;
        int row = 49 + rem / 16, q16 = (rem & 15) * 16;
        *reinterpret_cast<uint4*>(smc + OFF_V + tile * TILE + row * AST + q16) =
            make_uint4(0, 0, 0, 0);
    }
    // ---- Phase A: LayerNorm -> split-bf16 X tiles ----
    {
        float4 gg = *reinterpret_cast<const float4*>(&ln_g[lane * 4]);
        float4 bb = *reinterpret_cast<const float4*>(&ln_b[lane * 4]);
        for (int t = wid; t < 49; t += 16) {
            int r = wy * WSZ + t / WSZ, cp = wx * WSZ + t % WSZ;
            const float* xr = x + (size_t)(b * NPIX + r * HIMG + cp) * CDIM;
            float4 v = *reinterpret_cast<const float4*>(&xr[lane * 4]);
            float s = v.x + v.y + v.z + v.w;
            float q = v.x * v.x + v.y * v.y + v.z * v.z + v.w * v.w;
            #pragma unroll
            for (int o = 16; o; o >>= 1) {
                s += __shfl_xor_sync(0xffffffffu, s, o);
                q += __shfl_xor_sync(0xffffffffu, q, o);
            }
            float mu = s * (1.f / 128.f);
            float rs = rsqrtf(q * (1.f / 128.f) - mu * mu + LN_EPS);
            u32 h0, l0, h1, l1;
            split2((v.x - mu) * rs * gg.x + bb.x, (v.y - mu) * rs * gg.y + bb.y, h0, l0);
            split2((v.z - mu) * rs * gg.z + bb.z, (v.w - mu) * rs * gg.w + bb.w, h1, l1);
            char* p = smc + t * AST + lane * 8;
            *reinterpret_cast<uint2*>(p + OFF_XH) = make_uint2(h0, h1);
            *reinterpret_cast<uint2*>(p + OFF_XL) = make_uint2(l0, l1);
        }
    }
    __syncthreads();

    const int mband = wid >> 2, nq = wid & 3, tig = lane & 3, g = lane >> 2;

    // ---- Phase B: QKV GEMM, 6 chunks N=64, cp.async double-buffered ----
    for (int ch = 0; ch < 6; ++ch) {
        u32 wbase = smb + OFF_W0 + (ch & 1) * WBUFSZ;
        if (ch < 5) { CP_WAIT(1); } else { CP_WAIT(0); }
        __syncthreads();
        float d[2][4] = {};
        gemm_chunk(smb, wbase, lane, mband, nq, d);
        int R0 = mband * 16 + g, R1 = R0 + 8;
        #pragma unroll
        for (int nt = 0; nt < 2; ++nt) {
            int n = ch * 64 + nq * 16 + nt * 8 + 2 * tig;
            int base = OFF_Q + (n >> 7) * 2 * TILE, col = n & 127;
            float2 bq = *reinterpret_cast<const float2*>(bqkv + n);
            if (R0 < 49) {
                u32 uh, ul;
                split2(d[nt][0] + bq.x, d[nt][1] + bq.y, uh, ul);
                char* p = smc + base + R0 * AST + col * 2;
                *reinterpret_cast<u32*>(p) = uh;
                *reinterpret_cast<u32*>(p + TILE) = ul;
            }
            if (R1 < 49) {
                u32 uh, ul;
                split2(d[nt][2] + bq.x, d[nt][3] + bq.y, uh, ul);
                char* p = smc + base + R1 * AST + col * 2;
                *reinterpret_cast<u32*>(p) = uh;
                *reinterpret_cast<u32*>(p + TILE) = ul;
            }
        }
        __syncthreads();
        if (ch < 4) { cp_w(wbase, d_wqH, d_wqL, 384, (ch + 2) * 64, tid); CP_COMMIT(); }
    }
    // prefetch both wout chunks; they complete under the attention phase
    cp_w(smb + OFF_W0,          d_woH, d_woL, 128, 0,  tid); CP_COMMIT();
    cp_w(smb + OFF_W0 + WBUFSZ, d_woH, d_woL, 128, 64, tid); CP_COMMIT();

    // ---- Phase C: tensor-core attention; warp = (head, 2 q-bands) ----
    {
        const int head = wid & 7, half = wid >> 3;
        #pragma unroll
        for (int band = 0; band < 2; ++band) {
            int m0 = (half * 2 + band) * 16;
            u32 qh[4], ql[4];
            u32 aaddr = smb + OFF_Q + (m0 + (lane & 15)) * AST + head * 32 + (lane >> 4) * 16;
            ldsm4(qh, aaddr);
            ldsm4(ql, aaddr + TILE);
            float sd[7][4];
            #pragma unroll
            for (int nt = 0; nt < 7; ++nt) { sd[nt][0]=sd[nt][1]=sd[nt][2]=sd[nt][3]=0.f; }
            u32 baddr = smb + OFF_K + (lane & 7) * AST + head * 32 + ((lane >> 3) & 1) * 16;
            #pragma unroll
            for (int nt = 0; nt < 7; ++nt) {
                u32 bh[2], bl[2];
                ldsm2(bh, baddr + nt * 8 * AST);
                ldsm2(bl, baddr + nt * 8 * AST + TILE);
                mma16816(sd[nt], qh, bh);
                mma16816(sd[nt], qh, bl);
                mma16816(sd[nt], ql, bh);
            }
            float den0 = 0.f, den1 = 0.f;
            u32 Phg[8], Phg8[8], Plg[8], Plg8[8];
            #pragma unroll
            for (int nt = 0; nt < 7; ++nt) {
                float e0 = fexp(sd[nt][0] * SCALE_F);
                float e1 = fexp(sd[nt][1] * SCALE_F);
                float e2 = fexp(sd[nt][2] * SCALE_F);
                float e3 = fexp(sd[nt][3] * SCALE_F);
                if (nt == 6) {
                    bool v0 = tig == 0;
                    e0 = v0 ? e0 : 0.f; e2 = v0 ? e2 : 0.f;
                    e1 = 0.f; e3 = 0.f;
                }
                den0 += e0 + e1; den1 += e2 + e3;
                split2(e0, e1, Phg[nt], Plg[nt]);
                split2(e2, e3, Phg8[nt], Plg8[nt]);
            }
            Phg[7] = Plg[7] = Phg8[7] = Plg8[7] = 0u;
            den0 += __shfl_xor_sync(0xffffffffu, den0, 1);
            den0 += __shfl_xor_sync(0xffffffffu, den0, 2);
            den1 += __shfl_xor_sync(0xffffffffu, den1, 1);
            den1 += __shfl_xor_sync(0xffffffffu, den1, 2);
            float od[2][4] = {};
            #pragma unroll
            for (int kc = 0; kc < 4; ++kc) {
                u32 ah[4] = {Phg[2*kc], Phg8[2*kc], Phg[2*kc+1], Phg8[2*kc+1]};
                u32 al[4] = {Plg[2*kc], Plg8[2*kc], Plg[2*kc+1], Plg8[2*kc+1]};
                u32 vaddr = smb + OFF_V + (kc * 16 + (lane & 15)) * AST + head * 32;
                #pragma unroll
                for (int ntO = 0; ntO < 2; ++ntO) {
                    u32 vh[2], vl[2];
                    ldsm2t(vh, vaddr + ntO * 16);
                    ldsm2t(vl, vaddr + ntO * 16 + TILE);
                    mma16816(od[ntO], ah, vh);
                    mma16816(od[ntO], ah, vl);
                    mma16816(od[ntO], al, vh);
                }
            }
            float inv0 = __frcp_rn(den0), inv1 = __frcp_rn(den1);
            int r0 = m0 + g, r1 = r0 + 8;
            #pragma unroll
            for (int ntO = 0; ntO < 2; ++ntO) {
                int col = head * 16 + ntO * 8 + 2 * tig;
                if (r0 < 49) {
                    u32 uh, ul;
                    split2(od[ntO][0] * inv0, od[ntO][1] * inv0, uh, ul);
                    char* p = smc + r0 * AST + col * 2;
                    *reinterpret_cast<u32*>(p + OFF_XH) = uh;
                    *reinterpret_cast<u32*>(p + OFF_XL) = ul;
                }
                if (r1 < 49) {
                    u32 uh, ul;
                    split2(od[ntO][2] * inv1, od[ntO][3] * inv1, uh, ul);
                    char* p = smc + r1 * AST + col * 2;
                    *reinterpret_cast<u32*>(p + OFF_XH) = uh;
                    *reinterpret_cast<u32*>(p + OFF_XL) = ul;
                }
            }
        }
    }
    CP_WAIT(0);
    __syncthreads();

    // ---- Phase D: out-proj, both chunks resident; no inner barriers ----
    #pragma unroll
    for (int ch = 0; ch < 2; ++ch) {
        float d[2][4] = {};
        gemm_chunk(smb, smb + OFF_W0 + ch * WBUFSZ, lane, mband, nq, d);
        int R0 = mband * 16 + g, R1 = R0 + 8;
        #pragma unroll
        for (int nt = 0; nt < 2; ++nt) {
            int n = ch * 64 + nq * 16 + nt * 8 + 2 * tig;
            float2 bo = *reinterpret_cast<const float2*>(bout + n);
            if (R0 < 49) {
                int r = wy * WSZ + R0 / WSZ, cp = wx * WSZ + R0 % WSZ;
                *reinterpret_cast<float2*>(out + (size_t)(b * NPIX + r * HIMG + cp) * CDIM + n) =
                    make_float2(d[nt][0] + bo.x, d[nt][1] + bo.y);
            }
            if (R1 < 49) {
                int r = wy * WSZ + R1 / WSZ, cp = wx * WSZ + R1 % WSZ;
                *reinterpret_cast<float2*>(out + (size_t)(b * NPIX + r * HIMG + cp) * CDIM + n) =
                    make_float2(d[nt][2] + bo.x, d[nt][3] + bo.y);
            }
        }
    }
}

extern "C" void kernel_launch(void* const* d_in, const int* in_sizes, int n_in,
                              void* d_out, int out_size) {
    const float* x    = (const float*)d_in[0];
    const float* g    = (const float*)d_in[1];
    const float* bt   = (const float*)d_in[2];
    const float* wqkv = (const float*)d_in[3];
    const float* bqkv = (const float*)d_in[4];
    const float* wout = (const float*)d_in[5];
    const float* bout = (const float*)d_in[6];
    float* out = (float*)d_out;
    prep_w_kernel<<<256, 256>>>(wqkv, wout);
    cudaFuncSetAttribute(swin_mma_kernel,
                         cudaFuncAttributeMaxDynamicSharedMemorySize, SMEM_BYTES);
    swin_mma_kernel<<<4096, TPB, SMEM_BYTES>>>(x, g, bt, bqkv, bout, out);
}